// round 3
// baseline (speedup 1.0000x reference)
#include <cuda_runtime.h>
#include <cstdint>
#include <math.h>

#define Bb 64
#define Tt 512
#define Ff 256
#define Hh 512
#define GRIDN 128
#define NTHR 256
#define WROWS 24
#define WSTRIDE 1540                      // words/row: 768*2 splatted + 4 pad (bank skew 4)
#define SMEM_FLOATS (WROWS*WSTRIDE + Ff*Bb)
#define SMEM_BYTES  (SMEM_FLOATS*4)      // 147840 + 65536 = 213376

typedef unsigned long long ull;

// static device scratch (no allocations allowed)
__device__ float g_xT[Tt*Ff*Bb];          // [t][k][b]  33.5 MB
__device__ float g_h[2][2][Hh][Bb];       // [dir][slot][hcol][b]
__device__ ull   g_bar;                   // monotonic barrier counter (replay-safe)

// ---------------- PTX helpers ----------------
static __device__ __forceinline__ ull lds64(unsigned a) {
    ull v; asm("ld.shared.b64 %0, [%1];" : "=l"(v) : "r"(a)); return v;
}
static __device__ __forceinline__ void lds128(unsigned a, ull &x, ull &y) {
    asm("ld.shared.v2.b64 {%0,%1}, [%2];" : "=l"(x), "=l"(y) : "r"(a));
}
static __device__ __forceinline__ ull fma2(ull a, ull b, ull c) {
    ull d; asm("fma.rn.f32x2 %0, %1, %2, %3;" : "=l"(d) : "l"(a), "l"(b), "l"(c));
    return d;
}
static __device__ __forceinline__ float lof(ull x) { return __uint_as_float((unsigned)x); }
static __device__ __forceinline__ float hif(ull x) { return __uint_as_float((unsigned)(x >> 32)); }

// Grid-wide barrier: monotonic counter, never reset -> safe across graph replays.
static __device__ __forceinline__ void grid_barrier() {
    __threadfence();
    __syncthreads();
    if (threadIdx.x == 0) {
        ull old;
        asm volatile("atom.release.gpu.global.add.u64 %0, [%1], 1;"
                     : "=l"(old) : "l"(&g_bar) : "memory");
        ull target = (old / GRIDN + 1ULL) * GRIDN;
        ull cur = old + 1ULL;
        while (cur < target) {
            asm volatile("ld.acquire.gpu.global.u64 %0, [%1];"
                         : "=l"(cur) : "l"(&g_bar) : "memory");
            if (cur < target) __nanosleep(32);
        }
        __threadfence();
    }
    __syncthreads();
}

// ---------------- prologue: (B,T,F) -> xT[t][k][b] ----------------
extern "C" __global__ void __launch_bounds__(256)
gru_transpose(const float* __restrict__ data) {
    __shared__ float tile[64][65];
    const int t  = blockIdx.y;
    const int kc = blockIdx.x;           // k chunk of 64
    const int tid = threadIdx.x;
    for (int p = tid; p < 1024; p += 256) {
        int b  = p >> 4;
        int kk = (p & 15) * 4;
        float4 v = *(const float4*)(data + (size_t)b * (Tt * Ff) + (size_t)t * Ff + kc * 64 + kk);
        tile[kk + 0][b] = v.x; tile[kk + 1][b] = v.y;
        tile[kk + 2][b] = v.z; tile[kk + 3][b] = v.w;
    }
    __syncthreads();
    for (int p = tid; p < 1024; p += 256) {
        int r  = p >> 4;
        int c4 = (p & 15) * 4;
        float4 v = make_float4(tile[r][c4], tile[r][c4 + 1], tile[r][c4 + 2], tile[r][c4 + 3]);
        *(float4*)(g_xT + (size_t)t * (Ff * Bb) + (size_t)(kc * 64 + r) * Bb + c4) = v;
    }
}

// ---------------- persistent fused BiGRU ----------------
extern "C" __global__ void __launch_bounds__(NTHR, 1)
gru_persist(const float* __restrict__ Wi_f, const float* __restrict__ bi_f,
            const float* __restrict__ Wh_f, const float* __restrict__ bhn_f,
            const float* __restrict__ Wi_b, const float* __restrict__ bi_b,
            const float* __restrict__ Wh_b, const float* __restrict__ bhn_b,
            float* __restrict__ out) {
    extern __shared__ float smem[];
    float* Ws = smem;                        // [24][WSTRIDE] splatted weights
    float* Vs = smem + WROWS * WSTRIDE;      // [256][64] staged V chunk

    const int tid = threadIdx.x;
    const int bid = blockIdx.x;
    const int d   = bid >> 6;                // direction
    const int cb  = (bid & 63) * 8;          // h-column base

    const float* Wi  = d ? Wi_b  : Wi_f;
    const float* Wh  = d ? Wh_b  : Wh_f;
    const float* bi  = d ? bi_b  : bi_f;
    const float* bhn = d ? bhn_b : bhn_f;

    // stage splatted fused weights once: row j = gate*8+cc, k<256 Wi else Wh
    for (int idx = tid; idx < WROWS * 768; idx += NTHR) {
        int j = idx % WROWS;
        int k = idx / WROWS;
        int g = j >> 3, cc = j & 7;
        int gcol = g * Hh + cb + cc;
        float w = (k < Ff) ? Wi[(size_t)k * (3 * Hh) + gcol]
                           : Wh[(size_t)(k - Ff) * (3 * Hh) + gcol];
        Ws[j * WSTRIDE + 2 * k]     = w;
        Ws[j * WSTRIDE + 2 * k + 1] = w;
    }

    // zero my rows of h slot 0
    for (int i = tid; i < 8 * Bb; i += NTHR)
        g_h[d][0][cb + (i >> 6)][i & 63] = 0.f;

    // lane map: warp w -> bp in {8*(w/2)..+7}, c in {4*(w%2)..+3}
    const int w = tid >> 5, l = tid & 31;
    const int bp = ((w >> 1) << 3) | (l & 7);   // 0..31 (b pair)
    const int c  = ((w & 1) << 2) | (l >> 3);   // 0..7
    const int b0 = bp * 2;

    const float br = bi[cb + c];
    const float bz = bi[Hh + cb + c];
    const float bn = bi[2 * Hh + cb + c];
    const float bh = bhn[cb + c];

    const unsigned wsA = (unsigned)__cvta_generic_to_shared(Ws);
    const unsigned vsA = (unsigned)__cvta_generic_to_shared(Vs);
    const unsigned vBase  = vsA + (unsigned)b0 * 4u;
    const unsigned wrBase = wsA + (unsigned)((0  + c) * WSTRIDE) * 4u;
    const unsigned wzBase = wsA + (unsigned)((8  + c) * WSTRIDE) * 4u;
    const unsigned wnBase = wsA + (unsigned)((16 + c) * WSTRIDE) * 4u;

    grid_barrier();   // h zeros visible chip-wide

    for (int t = 0; t < Tt; ++t) {
        const int rs  = t & 1;
        const int ws2 = rs ^ 1;

        const float4* src0 = (const float4*)(g_xT + (size_t)t * (Ff * Bb));
        const float4* src1 = (const float4*)(&g_h[d][rs][0][0]);
        const float4* src2 = (const float4*)(&g_h[d][rs][256][0]);

        ull accR = 0, accZ = 0, accNX = 0, accNH = 0;

        #pragma unroll 1
        for (int ch = 0; ch < 3; ++ch) {
            const float4* s = (ch == 0) ? src0 : (ch == 1 ? src1 : src2);
            float4* dst = (float4*)Vs;
            #pragma unroll 4
            for (int i = tid; i < 4096; i += NTHR) dst[i] = __ldcg(s + i);
            __syncthreads();

            unsigned va = vBase;
            unsigned wr = wrBase + (unsigned)(ch * 256) * 8u;
            unsigned wz = wzBase + (unsigned)(ch * 256) * 8u;
            unsigned wn = wnBase + (unsigned)(ch * 256) * 8u;

            ull aR = accR, aZ = accZ, aN = (ch == 0) ? accNX : accNH;
            #pragma unroll 4
            for (int kk = 0; kk < 256; kk += 4) {
                ull v0 = lds64(va);
                ull v1 = lds64(va + 256);
                ull v2 = lds64(va + 512);
                ull v3 = lds64(va + 768);
                va += 1024;
                ull r0, r1, r2, r3, z0, z1, z2, z3, n0, n1, n2, n3;
                lds128(wr, r0, r1); lds128(wr + 16, r2, r3); wr += 32;
                lds128(wz, z0, z1); lds128(wz + 16, z2, z3); wz += 32;
                lds128(wn, n0, n1); lds128(wn + 16, n2, n3); wn += 32;
                aR = fma2(v0, r0, aR); aR = fma2(v1, r1, aR);
                aR = fma2(v2, r2, aR); aR = fma2(v3, r3, aR);
                aZ = fma2(v0, z0, aZ); aZ = fma2(v1, z1, aZ);
                aZ = fma2(v2, z2, aZ); aZ = fma2(v3, z3, aZ);
                aN = fma2(v0, n0, aN); aN = fma2(v1, n1, aN);
                aN = fma2(v2, n2, aN); aN = fma2(v3, n3, aN);
            }
            accR = aR; accZ = aZ;
            if (ch == 0) accNX = aN; else accNH = aN;
            __syncthreads();
        }

        // elementwise GRU cell for 2 (b) x 1 (c) cells
        float2 hp = *(const float2*)&g_h[d][rs][cb + c][b0];

        float r0v = 1.f / (1.f + expf(-(lof(accR) + br)));
        float r1v = 1.f / (1.f + expf(-(hif(accR) + br)));
        float z0v = 1.f / (1.f + expf(-(lof(accZ) + bz)));
        float z1v = 1.f / (1.f + expf(-(hif(accZ) + bz)));
        float n0v = tanhf(lof(accNX) + bn + r0v * (lof(accNH) + bh));
        float n1v = tanhf(hif(accNX) + bn + r1v * (hif(accNH) + bh));
        float h0 = (1.f - z0v) * n0v + z0v * hp.x;
        float h1 = (1.f - z1v) * n1v + z1v * hp.y;

        *(float2*)&g_h[d][ws2][cb + c][b0] = make_float2(h0, h1);

        size_t ob = (size_t)b0 * (Tt * 2 * Hh) + (size_t)t * (2 * Hh) + (size_t)d * Hh + cb + c;
        out[ob] = h0;
        out[ob + (size_t)(Tt * 2 * Hh)] = h1;

        if (t + 1 < Tt) grid_barrier();
    }
}

extern "C" void kernel_launch(void* const* d_in, const int* in_sizes, int n_in,
                              void* d_out, int out_size) {
    const float* data  = (const float*)d_in[0];
    const float* Wi_f  = (const float*)d_in[1];
    const float* bi_f  = (const float*)d_in[2];
    const float* Wh_f  = (const float*)d_in[3];
    const float* bhn_f = (const float*)d_in[4];
    const float* Wi_b  = (const float*)d_in[5];
    const float* bi_b  = (const float*)d_in[6];
    const float* Wh_b  = (const float*)d_in[7];
    const float* bhn_b = (const float*)d_in[8];
    float* out = (float*)d_out;

    cudaFuncSetAttribute(gru_persist, cudaFuncAttributeMaxDynamicSharedMemorySize, SMEM_BYTES);

    gru_transpose<<<dim3(Ff / 64, Tt), 256>>>(data);
    gru_persist<<<GRIDN, NTHR, SMEM_BYTES>>>(Wi_f, bi_f, Wh_f, bhn_f,
                                             Wi_b, bi_b, Wh_b, bhn_b, out);
}

// round 4
// speedup vs baseline: 1.2066x; 1.2066x over previous
#include <cuda_runtime.h>
#include <cstdint>
#include <math.h>

#define Bb 64
#define Tt 512
#define Ff 256
#define Hh 512
#define GRIDN 128
#define NTHR 512
#define WROWS 24
#define WSTRIDE 1540                       // words/row: 768*2 splatted + 4 pad
#define VSLOT_FLOATS 4096                  // 64 rows x 64 b
#define SMEM_FLOATS (WROWS*WSTRIDE + 4*VSLOT_FLOATS)
#define SMEM_BYTES  (SMEM_FLOATS*4)        // 147840 + 65536 = 213376
#define OST (Tt*2*Hh)                      // out stride per b

typedef unsigned long long ull;

// static device scratch
__device__ float g_xT[Tt*Ff*Bb];           // [t][k][b]
__device__ float g_h[2][2][Hh][Bb];        // [dir][slot][hcol][b]
__device__ ull   g_barc[2*16];             // per-direction monotonic counters (line-separated)

// ---------------- PTX helpers ----------------
static __device__ __forceinline__ ull lds64(unsigned a) {
    ull v; asm("ld.shared.b64 %0, [%1];" : "=l"(v) : "r"(a)); return v;
}
static __device__ __forceinline__ void lds128(unsigned a, ull &x, ull &y) {
    asm("ld.shared.v2.b64 {%0,%1}, [%2];" : "=l"(x), "=l"(y) : "r"(a));
}
static __device__ __forceinline__ ull fma2(ull a, ull b, ull c) {
    ull d; asm("fma.rn.f32x2 %0, %1, %2, %3;" : "=l"(d) : "l"(a), "l"(b), "l"(c));
    return d;
}
static __device__ __forceinline__ float lof(ull x) { return __uint_as_float((unsigned)x); }
static __device__ __forceinline__ float hif(ull x) { return __uint_as_float((unsigned)(x >> 32)); }

static __device__ __forceinline__ void cpa16(unsigned s, const float4* g) {
    asm volatile("cp.async.cg.shared.global [%0], [%1], 16;"
                 :: "r"(s), "l"(__cvta_generic_to_global((const void*)g)));
}
static __device__ __forceinline__ void cpa_commit() {
    asm volatile("cp.async.commit_group;");
}
template<int N> static __device__ __forceinline__ void cpa_wait() {
    asm volatile("cp.async.wait_group %0;" :: "n"(N));
}

static __device__ __forceinline__ float sigf(float x) {
    return __fdividef(1.f, 1.f + __expf(-x));
}
static __device__ __forceinline__ float tanf_fast(float x) {
    return __fdividef(2.f, 1.f + __expf(-2.f * x)) - 1.f;
}

// per-direction grid barrier: 64 arrivals, monotonic (graph-replay safe)
static __device__ __forceinline__ void grid_barrier(int d) {
    __threadfence();
    __syncthreads();
    if (threadIdx.x == 0) {
        ull* ctr = &g_barc[d * 16];
        ull old;
        asm volatile("atom.release.gpu.global.add.u64 %0, [%1], 1;"
                     : "=l"(old) : "l"(ctr) : "memory");
        ull target = (old / 64ULL + 1ULL) * 64ULL;
        ull cur = old + 1ULL;
        while (cur < target) {
            asm volatile("ld.acquire.gpu.global.u64 %0, [%1];"
                         : "=l"(cur) : "l"(ctr) : "memory");
            if (cur < target) __nanosleep(20);
        }
        __threadfence();
    }
    __syncthreads();
}

// ---------------- prologue: (B,T,F) -> xT[t][k][b] ----------------
extern "C" __global__ void __launch_bounds__(256)
gru_transpose(const float* __restrict__ data) {
    __shared__ float tile[64][65];
    const int t  = blockIdx.y;
    const int kc = blockIdx.x;
    const int tid = threadIdx.x;
    for (int p = tid; p < 1024; p += 256) {
        int b  = p >> 4;
        int kk = (p & 15) * 4;
        float4 v = *(const float4*)(data + (size_t)b * (Tt * Ff) + (size_t)t * Ff + kc * 64 + kk);
        tile[kk + 0][b] = v.x; tile[kk + 1][b] = v.y;
        tile[kk + 2][b] = v.z; tile[kk + 3][b] = v.w;
    }
    __syncthreads();
    for (int p = tid; p < 1024; p += 256) {
        int r  = p >> 4;
        int c4 = (p & 15) * 4;
        float4 v = make_float4(tile[r][c4], tile[r][c4 + 1], tile[r][c4 + 2], tile[r][c4 + 3]);
        *(float4*)(g_xT + (size_t)t * (Ff * Bb) + (size_t)(kc * 64 + r) * Bb + c4) = v;
    }
}

// ---------------- persistent fused BiGRU (split-K, cp.async pipelined) ----------------
extern "C" __global__ void __launch_bounds__(NTHR, 1)
gru_persist(const float* __restrict__ Wi_f, const float* __restrict__ bi_f,
            const float* __restrict__ Wh_f, const float* __restrict__ bhn_f,
            const float* __restrict__ Wi_b, const float* __restrict__ bi_b,
            const float* __restrict__ Wh_b, const float* __restrict__ bhn_b,
            float* __restrict__ out) {
    extern __shared__ float smem[];
    float* Ws = smem;                         // [24][WSTRIDE] splatted weights
    float* Vs = smem + WROWS * WSTRIDE;       // 4 x [64][64] V slots

    const int tid = threadIdx.x;
    const int bid = blockIdx.x;
    const int d   = bid >> 6;
    const int cb  = (bid & 63) * 8;

    const float* Wi  = d ? Wi_b  : Wi_f;
    const float* Wh  = d ? Wh_b  : Wh_f;
    const float* bi  = d ? bi_b  : bi_f;
    const float* bhn = d ? bhn_b : bhn_f;

    // stage splatted fused weights once
    for (int idx = tid; idx < WROWS * 768; idx += NTHR) {
        int j = idx % WROWS;
        int k = idx / WROWS;
        int g = j >> 3, cc = j & 7;
        int gcol = g * Hh + cb + cc;
        float w = (k < Ff) ? Wi[(size_t)k * (3 * Hh) + gcol]
                           : Wh[(size_t)(k - Ff) * (3 * Hh) + gcol];
        Ws[j * WSTRIDE + 2 * k]     = w;
        Ws[j * WSTRIDE + 2 * k + 1] = w;
    }

    // zero my rows of h slot 0
    for (int i = tid; i < 8 * Bb; i += NTHR)
        g_h[d][0][cb + (i >> 6)][i & 63] = 0.f;

    // split-K: half hk handles k in [hk*384, hk*384+384)
    const int hk   = tid >> 8;
    const int tid2 = tid & 255;
    const int w2 = tid2 >> 5, l = tid2 & 31;
    const int bp = ((w2 >> 1) << 3) | (l & 7);
    const int c  = ((w2 & 1) << 2) | (l >> 3);
    const int b0 = bp * 2;

    const float br = bi[cb + c];
    const float bz = bi[Hh + cb + c];
    const float bn = bi[2 * Hh + cb + c];
    const float bh = bhn[cb + c];

    const unsigned wsA = (unsigned)__cvta_generic_to_shared(Ws);
    const unsigned vsA = (unsigned)__cvta_generic_to_shared(Vs);
    const unsigned vOff   = (unsigned)b0 * 4u;
    const unsigned wrBase = wsA + (unsigned)((0  + c) * WSTRIDE) * 4u;
    const unsigned wzBase = wsA + (unsigned)((8  + c) * WSTRIDE) * 4u;
    const unsigned wnBase = wsA + (unsigned)((16 + c) * WSTRIDE) * 4u;

    grid_barrier(d);

    for (int t = 0; t < Tt; ++t) {
        const int rs  = t & 1;
        const int ws2 = rs ^ 1;
        const float* hbase = &g_h[d][rs][0][0];
        const float* xbase = g_xT + (size_t)t * (Ff * Bb);

        // stage pair j: chunk A rows 64j (half0), chunk B rows 384+64j (half1)
        #define STAGE_PAIR(J)                                                          \
        {                                                                              \
            const int sA = (2*(J)) & 3, sB = (2*(J)+1) & 3;                            \
            const int rowA = 64*(J), rowB = 384 + 64*(J);                              \
            const float4* srcA = (rowA < 256)                                          \
                ? (const float4*)(xbase + rowA * Bb)                                   \
                : (const float4*)(hbase + (rowA - 256) * Bb);                          \
            const float4* srcB = (const float4*)(hbase + (rowB - 256) * Bb);           \
            unsigned dA = vsA + (unsigned)sA * 16384u;                                 \
            unsigned dB = vsA + (unsigned)sB * 16384u;                                 \
            for (int i = tid; i < 1024; i += NTHR) {                                   \
                cpa16(dA + (unsigned)i * 16u, srcA + i);                               \
                cpa16(dB + (unsigned)i * 16u, srcB + i);                               \
            }                                                                          \
            cpa_commit();                                                              \
        }

        STAGE_PAIR(0)
        STAGE_PAIR(1)

        ull aR = 0, aZ = 0, aN = 0, aNX = 0;

        #pragma unroll 1
        for (int j = 0; j < 6; ++j) {
            if (j < 5) cpa_wait<1>(); else cpa_wait<0>();
            __syncthreads();

            const int slot = (2 * j + hk) & 3;
            const int k0   = hk * 384 + j * 64;
            unsigned va = vsA + (unsigned)slot * 16384u + vOff;
            unsigned wr = wrBase + (unsigned)k0 * 8u;
            unsigned wz = wzBase + (unsigned)k0 * 8u;
            unsigned wn = wnBase + (unsigned)k0 * 8u;

            #pragma unroll 4
            for (int kk = 0; kk < 64; kk += 4) {
                ull v0 = lds64(va);
                ull v1 = lds64(va + 256);
                ull v2 = lds64(va + 512);
                ull v3 = lds64(va + 768);
                va += 1024;
                ull r0, r1, r2, r3, z0, z1, z2, z3, n0, n1, n2, n3;
                lds128(wr, r0, r1); lds128(wr + 16, r2, r3); wr += 32;
                lds128(wz, z0, z1); lds128(wz + 16, z2, z3); wz += 32;
                lds128(wn, n0, n1); lds128(wn + 16, n2, n3); wn += 32;
                aR = fma2(v0, r0, aR); aR = fma2(v1, r1, aR);
                aR = fma2(v2, r2, aR); aR = fma2(v3, r3, aR);
                aZ = fma2(v0, z0, aZ); aZ = fma2(v1, z1, aZ);
                aZ = fma2(v2, z2, aZ); aZ = fma2(v3, z3, aZ);
                aN = fma2(v0, n0, aN); aN = fma2(v1, n1, aN);
                aN = fma2(v2, n2, aN); aN = fma2(v3, n3, aN);
            }
            if (hk == 0 && j == 3) { aNX = aN; aN = 0; }   // x-part of n done

            __syncthreads();
            if (j < 4) {
                const int jn = j + 2;
                switch (jn) {
                    case 2: STAGE_PAIR(2) break;
                    case 3: STAGE_PAIR(3) break;
                    case 4: STAGE_PAIR(4) break;
                    default: STAGE_PAIR(5) break;
                }
            }
        }

        // cross-half reduction in smem (slots are free now)
        ull* red = (ull*)Vs;
        if (hk) {
            red[tid2 * 3 + 0] = aR;
            red[tid2 * 3 + 1] = aZ;
            red[tid2 * 3 + 2] = aN;
        }
        __syncthreads();

        if (hk == 0) {
            float sR0 = lof(aR) + lof(red[tid2 * 3 + 0]);
            float sR1 = hif(aR) + hif(red[tid2 * 3 + 0]);
            float sZ0 = lof(aZ) + lof(red[tid2 * 3 + 1]);
            float sZ1 = hif(aZ) + hif(red[tid2 * 3 + 1]);
            float sH0 = lof(aN) + lof(red[tid2 * 3 + 2]);
            float sH1 = hif(aN) + hif(red[tid2 * 3 + 2]);

            float2 hp = *(const float2*)&g_h[d][rs][cb + c][b0];

            float r0v = sigf(sR0 + br);
            float r1v = sigf(sR1 + br);
            float z0v = sigf(sZ0 + bz);
            float z1v = sigf(sZ1 + bz);
            float n0v = tanf_fast(lof(aNX) + bn + r0v * (sH0 + bh));
            float n1v = tanf_fast(hif(aNX) + bn + r1v * (sH1 + bh));
            float h0 = (1.f - z0v) * n0v + z0v * hp.x;
            float h1 = (1.f - z1v) * n1v + z1v * hp.y;

            *(float2*)&g_h[d][ws2][cb + c][b0] = make_float2(h0, h1);

            size_t ob = (size_t)b0 * OST + (size_t)t * (2 * Hh) + (size_t)d * Hh + cb + c;
            out[ob] = h0;
            out[ob + (size_t)OST] = h1;
        }

        grid_barrier(d);
        #undef STAGE_PAIR
    }
}

extern "C" void kernel_launch(void* const* d_in, const int* in_sizes, int n_in,
                              void* d_out, int out_size) {
    const float* data  = (const float*)d_in[0];
    const float* Wi_f  = (const float*)d_in[1];
    const float* bi_f  = (const float*)d_in[2];
    const float* Wh_f  = (const float*)d_in[3];
    const float* bhn_f = (const float*)d_in[4];
    const float* Wi_b  = (const float*)d_in[5];
    const float* bi_b  = (const float*)d_in[6];
    const float* Wh_b  = (const float*)d_in[7];
    const float* bhn_b = (const float*)d_in[8];
    float* out = (float*)d_out;

    cudaFuncSetAttribute(gru_persist, cudaFuncAttributeMaxDynamicSharedMemorySize, SMEM_BYTES);

    gru_transpose<<<dim3(Ff / 64, Tt), 256>>>(data);
    gru_persist<<<GRIDN, NTHR, SMEM_BYTES>>>(Wi_f, bi_f, Wh_f, bhn_f,
                                             Wi_b, bi_b, Wh_b, bhn_b, out);
}

// round 7
// speedup vs baseline: 1.6850x; 1.3965x over previous
#include <cuda_runtime.h>
#include <cstdint>
#include <math.h>

#define Bb 64
#define Tt 512
#define Ff 256
#define Hh 512
#define TFs (Tt*Ff)
#define GRIDN 128
#define NTHR 512
#define WSTRIDE 772                 // floats per weight row (768 + 4 pad)
#define VROWB 272                   // bytes per b-row in V slot (68 floats)
#define VSLOTB 17408                // 64 rows * 272 B
#define WS_BYTES (24*WSTRIDE*4)     // 74112
#define SMEM_BYTES (WS_BYTES + 8*VSLOTB)   // 74112 + 139264 = 213376
#define OST (Tt*2*Hh)

typedef unsigned long long ull;

// static device scratch (no allocations allowed)
__device__ float g_h[2][2][Bb][Hh];   // [dir][slot][b][hcol]  (k-major per b)
__device__ ull   g_barc[32];          // per-direction monotonic counters (line-separated)

// ---------------- helpers ----------------
static __device__ __forceinline__ ull fma2(ull a, ull b, ull c) {
    ull d; asm("fma.rn.f32x2 %0, %1, %2, %3;" : "=l"(d) : "l"(a), "l"(b), "l"(c));
    return d;
}
static __device__ __forceinline__ void add2(ull &a, ull b) {
    asm("add.rn.f32x2 %0, %0, %1;" : "+l"(a) : "l"(b));
}
static __device__ __forceinline__ float lof(ull x) { return __uint_as_float((unsigned)x); }
static __device__ __forceinline__ float hif(ull x) { return __uint_as_float((unsigned)(x >> 32)); }

// VOLATILE shared load with literal immediate offset.
// volatile is load-bearing: a non-volatile asm with only register operands is
// "pure" to the compiler and may be hoisted ACROSS the volatile barrier asms
// (barp/cpa_wait), reading the V slot before cp.async fills it. That was the
// R5/R6 correctness bug. Volatile asms cannot be reordered w.r.t. each other.
#define LDS128O(base, O, a, b) \
    asm volatile("ld.shared.v2.b64 {%0,%1}, [%2+" #O "];" : "=l"(a), "=l"(b) : "r"(base))

static __device__ __forceinline__ void cpa16(unsigned s, const float4* g) {
    asm volatile("cp.async.cg.shared.global [%0], [%1], 16;"
                 :: "r"(s), "l"(__cvta_generic_to_global((const void*)g)));
}
static __device__ __forceinline__ void cpa_commit() {
    asm volatile("cp.async.commit_group;");
}
template<int N> static __device__ __forceinline__ void cpa_wait() {
    asm volatile("cp.async.wait_group %0;" :: "n"(N) : "memory");
}

static __device__ __forceinline__ float sigf(float x) {
    return __fdividef(1.f, 1.f + __expf(-x));
}
static __device__ __forceinline__ float tanf_fast(float x) {
    return __fdividef(2.f, 1.f + __expf(-2.f * x)) - 1.f;
}

// partition-scoped barrier (128 threads), ids 1..4
static __device__ __forceinline__ void barp(int p) {
    asm volatile("bar.sync %0, 128;" :: "r"(p + 1) : "memory");
}

// per-direction grid barrier: 64 arrivals, monotonic (graph-replay safe).
static __device__ __forceinline__ void grid_barrier(int d) {
    __threadfence();
    __syncthreads();
    if (threadIdx.x == 0) {
        ull* ctr = &g_barc[d * 16];
        ull old;
        asm volatile("atom.release.gpu.global.add.u64 %0, [%1], 1;"
                     : "=l"(old) : "l"(ctr) : "memory");
        ull target = (old / 64ULL + 1ULL) * 64ULL;
        ull cur = old + 1ULL;
        while (cur < target) {
            asm volatile("ld.acquire.gpu.global.u64 %0, [%1];"
                         : "=l"(cur) : "l"(ctr) : "memory");
            if (cur < target) __nanosleep(20);
        }
        __threadfence();
    }
    __syncthreads();
}

// stage one 64k x 64b chunk into a V slot (k-major rows, 68-float padded)
static __device__ __forceinline__ void stage_chunk(unsigned dst, const float* sb,
                                                   int sstr, int tid2) {
#pragma unroll
    for (int j = 0; j < 8; ++j) {
        int idx = tid2 + j * 128;
        int b = idx >> 4, f = idx & 15;
        cpa16(dst + (unsigned)(b * VROWB + f * 16),
              (const float4*)(sb + (size_t)b * sstr) + f);
    }
    cpa_commit();
}

// one 4-k micro-iter: 7 LDS.128 + 24 fma.f32x2 (4 b x 3 gates, k-packed)
#define GITER(O) { ull x0,x1,y0,y1,u0,u1,v0,v1,q0,q1,s0,s1,w0,w1; \
  LDS128O(va0,O,x0,x1); LDS128O(va1,O,y0,y1); \
  LDS128O(va2,O,u0,u1); LDS128O(va3,O,v0,v1); \
  LDS128O(wra,O,q0,q1); LDS128O(wza,O,s0,s1); LDS128O(wna,O,w0,w1); \
  aR0=fma2(x0,q0,aR0); aR0=fma2(x1,q1,aR0); \
  aR1=fma2(y0,q0,aR1); aR1=fma2(y1,q1,aR1); \
  aR2=fma2(u0,q0,aR2); aR2=fma2(u1,q1,aR2); \
  aR3=fma2(v0,q0,aR3); aR3=fma2(v1,q1,aR3); \
  aZ0=fma2(x0,s0,aZ0); aZ0=fma2(x1,s1,aZ0); \
  aZ1=fma2(y0,s0,aZ1); aZ1=fma2(y1,s1,aZ1); \
  aZ2=fma2(u0,s0,aZ2); aZ2=fma2(u1,s1,aZ2); \
  aZ3=fma2(v0,s0,aZ3); aZ3=fma2(v1,s1,aZ3); \
  nl0=fma2(x0,w0,nl0); nl0=fma2(x1,w1,nl0); \
  nl1=fma2(y0,w0,nl1); nl1=fma2(y1,w1,nl1); \
  nl2=fma2(u0,w0,nl2); nl2=fma2(u1,w1,nl2); \
  nl3=fma2(v0,w0,nl3); nl3=fma2(v1,w1,nl3); }

#define COMPUTE_CHUNK(SLOTBASE, KK) { \
  const unsigned va0 = (SLOTBASE) + vb0, va1 = (SLOTBASE) + vb1, \
                 va2 = (SLOTBASE) + vb2, va3 = (SLOTBASE) + vb3; \
  const unsigned wra = wrB + (unsigned)(KK) * 4u, \
                 wza = wzB + (unsigned)(KK) * 4u, \
                 wna = wnB + (unsigned)(KK) * 4u; \
  ull nl0 = 0, nl1 = 0, nl2 = 0, nl3 = 0; \
  GITER(0)   GITER(16)  GITER(32)  GITER(48) \
  GITER(64)  GITER(80)  GITER(96)  GITER(112) \
  GITER(128) GITER(144) GITER(160) GITER(176) \
  GITER(192) GITER(208) GITER(224) GITER(240) \
  if ((KK) < Ff) { add2(aNX0,nl0); add2(aNX1,nl1); add2(aNX2,nl2); add2(aNX3,nl3); } \
  else           { add2(aNH0,nl0); add2(aNH1,nl1); add2(aNH2,nl2); add2(aNH3,nl3); } }

// epilogue for one of the thread's 4 b cells (partition 0 only)
#define EPI(G, AR, AZ, AX, AH) { \
  ull R = AR, Z = AZ, X = AX, Hc = AH; \
  _Pragma("unroll") \
  for (int q = 0; q < 3; ++q) { \
    const ull* e = red + (size_t)q * 128 + tid2; \
    add2(R,  e[(G)      * 384]); add2(Z,  e[(4 + (G))  * 384]); \
    add2(X,  e[(8 + (G))* 384]); add2(Hc, e[(12 + (G))* 384]); } \
  float sR = lof(R) + hif(R), sZ = lof(Z) + hif(Z); \
  float sX = lof(X) + hif(X), sH = lof(Hc) + hif(Hc); \
  float rv = sigf(sR + br), zv = sigf(sZ + bz); \
  float nv = tanf_fast(sX + bn + rv * (sH + bh)); \
  int bq = bb + 16 * (G); \
  float hprev = g_h[d][rs][bq][cb + c]; \
  float hnew = (1.f - zv) * nv + zv * hprev; \
  g_h[d][ws][bq][cb + c] = hnew; \
  out[(size_t)bq * OST + (size_t)t * (2 * Hh) + (size_t)d * Hh + cb + c] = hnew; }

// ---------------- persistent fused BiGRU ----------------
extern "C" __global__ void __launch_bounds__(NTHR, 1)
gru_persist(const float* __restrict__ data,
            const float* __restrict__ Wi_f, const float* __restrict__ bi_f,
            const float* __restrict__ Wh_f, const float* __restrict__ bhn_f,
            const float* __restrict__ Wi_b, const float* __restrict__ bi_b,
            const float* __restrict__ Wh_b, const float* __restrict__ bhn_b,
            float* __restrict__ out) {
    extern __shared__ float smem[];
    float* Ws  = smem;                               // [24][772]
    ull*   red = (ull*)(smem + 24 * WSTRIDE);        // reduction area (in V region)

    const int tid = threadIdx.x;
    const int bid = blockIdx.x;
    const int d   = bid >> 6;                 // direction
    const int cb  = (bid & 63) * 8;           // h-column base (8 columns per block)

    const float* Wi  = d ? Wi_b  : Wi_f;
    const float* Wh  = d ? Wh_b  : Wh_f;
    const float* bi  = d ? bi_b  : bi_f;
    const float* bhn = d ? bhn_b : bhn_f;

    // stage fused weights once: row j = gate*8 + cc, k-major, unsplatted
    for (int idx = tid; idx < 24 * 768; idx += NTHR) {
        int k = idx / 24, j = idx - k * 24;
        int g = j >> 3, cc = j & 7;
        int gcol = g * Hh + cb + cc;
        Ws[j * WSTRIDE + k] = (k < Ff) ? Wi[(size_t)k * (3 * Hh) + gcol]
                                       : Wh[(size_t)(k - Ff) * (3 * Hh) + gcol];
    }

    // zero my 8 h-columns of slot 0
    for (int i = tid; i < Bb * 8; i += NTHR)
        g_h[d][0][i >> 3][cb + (i & 7)] = 0.f;

    // split-K4 partitions: p handles k in [p*192, p*192+192)
    const int p    = tid >> 7;
    const int tid2 = tid & 127;
    const int c    = tid2 >> 4;     // 0..7  (h-column within block)
    const int bb   = tid2 & 15;     // b base; thread's b's: bb, bb+16, bb+32, bb+48

    const float br = bi[cb + c];
    const float bz = bi[Hh + cb + c];
    const float bn = bi[2 * Hh + cb + c];
    const float bh = bhn[cb + c];

    const unsigned wsA = (unsigned)__cvta_generic_to_shared(Ws);
    const unsigned vsA = (unsigned)__cvta_generic_to_shared(smem + 24 * WSTRIDE);
    const unsigned vb0 = (unsigned)(bb        * VROWB);
    const unsigned vb1 = (unsigned)((bb + 16) * VROWB);
    const unsigned vb2 = (unsigned)((bb + 32) * VROWB);
    const unsigned vb3 = (unsigned)((bb + 48) * VROWB);
    const unsigned wrB = wsA + (unsigned)((0  + c) * WSTRIDE) * 4u;
    const unsigned wzB = wsA + (unsigned)((8  + c) * WSTRIDE) * 4u;
    const unsigned wnB = wsA + (unsigned)((16 + c) * WSTRIDE) * 4u;

    const int K0 = p * 192, K1 = K0 + 64, K2 = K0 + 128;
    const unsigned slotA = vsA + (unsigned)(2 * p)     * VSLOTB;
    const unsigned slotB = vsA + (unsigned)(2 * p + 1) * VSLOTB;

    grid_barrier(d);   // h zeros + weights visible

    for (int t = 0; t < Tt; ++t) {
        const int rs = t & 1;
        const int ws = rs ^ 1;
        const float* hbase = &g_h[d][rs][0][0];
        const float* xbase = data + (size_t)t * Ff;

        // stage chunk sources: x if k<256 else h (rows are contiguous both ways)
        #define SRCP(KX)  (((KX) < Ff) ? (xbase + (KX)) : (hbase + ((KX) - Ff)))
        #define SSTR(KX)  (((KX) < Ff) ? TFs : Hh)

        stage_chunk(slotA, SRCP(K0), SSTR(K0), tid2);
        stage_chunk(slotB, SRCP(K1), SSTR(K1), tid2);

        ull aR0=0,aR1=0,aR2=0,aR3=0, aZ0=0,aZ1=0,aZ2=0,aZ3=0;
        ull aNX0=0,aNX1=0,aNX2=0,aNX3=0, aNH0=0,aNH1=0,aNH2=0,aNH3=0;

        cpa_wait<1>(); barp(p);
        COMPUTE_CHUNK(slotA, K0);
        barp(p);
        stage_chunk(slotA, SRCP(K2), SSTR(K2), tid2);

        cpa_wait<1>(); barp(p);
        COMPUTE_CHUNK(slotB, K1);

        cpa_wait<0>(); barp(p);
        COMPUTE_CHUNK(slotA, K2);

        __syncthreads();

        if (p) {   // partitions 1..3 publish partials (conflict-free layout)
            ull* rp = red + (size_t)(p - 1) * 128 + tid2;
            rp[0*384]=aR0;  rp[1*384]=aR1;  rp[2*384]=aR2;  rp[3*384]=aR3;
            rp[4*384]=aZ0;  rp[5*384]=aZ1;  rp[6*384]=aZ2;  rp[7*384]=aZ3;
            rp[8*384]=aNX0; rp[9*384]=aNX1; rp[10*384]=aNX2; rp[11*384]=aNX3;
            rp[12*384]=aNH0; rp[13*384]=aNH1; rp[14*384]=aNH2; rp[15*384]=aNH3;
        }
        __syncthreads();

        if (p == 0) {
            EPI(0, aR0, aZ0, aNX0, aNH0)
            EPI(1, aR1, aZ1, aNX1, aNH1)
            EPI(2, aR2, aZ2, aNX2, aNH2)
            EPI(3, aR3, aZ3, aNX3, aNH3)
        }

        grid_barrier(d);
        #undef SRCP
        #undef SSTR
    }
}

extern "C" void kernel_launch(void* const* d_in, const int* in_sizes, int n_in,
                              void* d_out, int out_size) {
    const float* data  = (const float*)d_in[0];
    const float* Wi_f  = (const float*)d_in[1];
    const float* bi_f  = (const float*)d_in[2];
    const float* Wh_f  = (const float*)d_in[3];
    const float* bhn_f = (const float*)d_in[4];
    const float* Wi_b  = (const float*)d_in[5];
    const float* bi_b  = (const float*)d_in[6];
    const float* Wh_b  = (const float*)d_in[7];
    const float* bhn_b = (const float*)d_in[8];
    float* out = (float*)d_out;

    cudaFuncSetAttribute(gru_persist, cudaFuncAttributeMaxDynamicSharedMemorySize, SMEM_BYTES);

    gru_persist<<<GRIDN, NTHR, SMEM_BYTES>>>(data, Wi_f, bi_f, Wh_f, bhn_f,
                                             Wi_b, bi_b, Wh_b, bhn_b, out);
}

// round 8
// speedup vs baseline: 1.7787x; 1.0556x over previous
#include <cuda_runtime.h>
#include <cstdint>
#include <math.h>

#define Bb 64
#define Tt 512
#define Ff 256
#define Hh 512
#define TFs (Tt*Ff)
#define GRIDN 128
#define NTHR 768
#define WSTRIDE 772                 // floats per weight row (768 + 4 pad)
#define VROWB 144                   // bytes per b-row in a 32-k slot (36 floats)
#define VSLOTB 9216                 // 64 rows * 144 B
#define WS_BYTES (24*WSTRIDE*4)     // 74112
#define SMEM_BYTES (WS_BYTES + 12*VSLOTB)  // 74112 + 110592 = 184704
#define OST (Tt*2*Hh)

typedef unsigned long long ull;

// static device scratch (no allocations allowed)
__device__ float g_h[2][2][Bb][Hh];   // [dir][slot][b][hcol]
__device__ ull   g_barc[32];          // per-direction monotonic counters

// ---------------- helpers ----------------
static __device__ __forceinline__ ull fma2(ull a, ull b, ull c) {
    ull d; asm("fma.rn.f32x2 %0, %1, %2, %3;" : "=l"(d) : "l"(a), "l"(b), "l"(c));
    return d;
}
static __device__ __forceinline__ void add2(ull &a, ull b) {
    asm("add.rn.f32x2 %0, %0, %1;" : "+l"(a) : "l"(b));
}
static __device__ __forceinline__ float lof(ull x) { return __uint_as_float((unsigned)x); }
static __device__ __forceinline__ float hif(ull x) { return __uint_as_float((unsigned)(x >> 32)); }

// VOLATILE shared load (load-bearing: prevents hoisting across barrier asms —
// the R5/R6 correctness bug).
#define LDS128O(base, O, a, b) \
    asm volatile("ld.shared.v2.b64 {%0,%1}, [%2+" #O "];" : "=l"(a), "=l"(b) : "r"(base))

static __device__ __forceinline__ void cpa16(unsigned s, const float4* g) {
    asm volatile("cp.async.cg.shared.global [%0], [%1], 16;"
                 :: "r"(s), "l"(__cvta_generic_to_global((const void*)g)));
}
static __device__ __forceinline__ void cpa_commit() {
    asm volatile("cp.async.commit_group;");
}
template<int N> static __device__ __forceinline__ void cpa_wait() {
    asm volatile("cp.async.wait_group %0;" :: "n"(N) : "memory");
}

static __device__ __forceinline__ float sigf(float x) {
    return __fdividef(1.f, 1.f + __expf(-x));
}
static __device__ __forceinline__ float tanf_fast(float x) {
    return __fdividef(2.f, 1.f + __expf(-2.f * x)) - 1.f;
}

// partition-scoped barrier (128 threads), ids 1..6
static __device__ __forceinline__ void barp(int p) {
    asm volatile("bar.sync %0, 128;" :: "r"(p + 1) : "memory");
}

// per-direction grid barrier: 64 arrivals, monotonic (graph-replay safe)
static __device__ __forceinline__ void grid_barrier(int d) {
    __threadfence();
    __syncthreads();
    if (threadIdx.x == 0) {
        ull* ctr = &g_barc[d * 16];
        ull old;
        asm volatile("atom.release.gpu.global.add.u64 %0, [%1], 1;"
                     : "=l"(old) : "l"(ctr) : "memory");
        ull target = (old / 64ULL + 1ULL) * 64ULL;
        ull cur = old + 1ULL;
        while (cur < target) {
            asm volatile("ld.acquire.gpu.global.u64 %0, [%1];"
                         : "=l"(cur) : "l"(ctr) : "memory");
            if (cur < target) __nanosleep(20);
        }
        __threadfence();
    }
    __syncthreads();
}

// stage one 32k x 64b chunk (8 KB) into a slot; 4 cp.async per thread
static __device__ __forceinline__ void stage32(unsigned dst, const float* sb,
                                               int sstr, int tid2) {
#pragma unroll
    for (int j = 0; j < 4; ++j) {
        int idx = tid2 + j * 128;
        int b = idx >> 3, f = idx & 7;
        cpa16(dst + (unsigned)(b * VROWB + f * 16),
              (const float4*)(sb + (size_t)b * sstr) + f);
    }
    cpa_commit();
}

// one 4-k micro-iter: 7 LDS.128 + 24 fma.f32x2 (4 b x 3 gates)
#define GITER(O) { ull x0,x1,y0,y1,u0,u1,v0,v1,q0,q1,s0,s1,w0,w1; \
  LDS128O(va0,O,x0,x1); LDS128O(va1,O,y0,y1); \
  LDS128O(va2,O,u0,u1); LDS128O(va3,O,v0,v1); \
  LDS128O(wra,O,q0,q1); LDS128O(wza,O,s0,s1); LDS128O(wna,O,w0,w1); \
  aR0=fma2(x0,q0,aR0); aR0=fma2(x1,q1,aR0); \
  aR1=fma2(y0,q0,aR1); aR1=fma2(y1,q1,aR1); \
  aR2=fma2(u0,q0,aR2); aR2=fma2(u1,q1,aR2); \
  aR3=fma2(v0,q0,aR3); aR3=fma2(v1,q1,aR3); \
  aZ0=fma2(x0,s0,aZ0); aZ0=fma2(x1,s1,aZ0); \
  aZ1=fma2(y0,s0,aZ1); aZ1=fma2(y1,s1,aZ1); \
  aZ2=fma2(u0,s0,aZ2); aZ2=fma2(u1,s1,aZ2); \
  aZ3=fma2(v0,s0,aZ3); aZ3=fma2(v1,s1,aZ3); \
  aN0=fma2(x0,w0,aN0); aN0=fma2(x1,w1,aN0); \
  aN1=fma2(y0,w0,aN1); aN1=fma2(y1,w1,aN1); \
  aN2=fma2(u0,w0,aN2); aN2=fma2(u1,w1,aN2); \
  aN3=fma2(v0,w0,aN3); aN3=fma2(v1,w1,aN3); }

// one 32-k chunk: 8 GITERs
#define COMPUTE_CHUNK(SLOTBASE, KK) { \
  const unsigned va0 = (SLOTBASE) + vb0, va1 = (SLOTBASE) + vb1, \
                 va2 = (SLOTBASE) + vb2, va3 = (SLOTBASE) + vb3; \
  const unsigned wra = wrB + (unsigned)(KK) * 4u, \
                 wza = wzB + (unsigned)(KK) * 4u, \
                 wna = wnB + (unsigned)(KK) * 4u; \
  GITER(0)  GITER(16) GITER(32) GITER(48) \
  GITER(64) GITER(80) GITER(96) GITER(112) }

// epilogue for one of the thread's 4 b cells (partition 0 only).
// q=0 -> p1 (x-type N); q=1..4 -> p2..p5 (h-type N)
#define EPI(G, AR, AZ, AN) { \
  ull R = AR, Z = AZ; \
  _Pragma("unroll") \
  for (int q = 0; q < 5; ++q) { \
    const ull* e = red + (size_t)q * 1536 + tid2; \
    add2(R, e[(G) * 128]); add2(Z, e[(4 + (G)) * 128]); } \
  ull X = AN; add2(X, red[(size_t)0 * 1536 + (8 + (G)) * 128 + tid2]); \
  ull Hc = red[(size_t)1 * 1536 + (8 + (G)) * 128 + tid2]; \
  add2(Hc, red[(size_t)2 * 1536 + (8 + (G)) * 128 + tid2]); \
  add2(Hc, red[(size_t)3 * 1536 + (8 + (G)) * 128 + tid2]); \
  add2(Hc, red[(size_t)4 * 1536 + (8 + (G)) * 128 + tid2]); \
  float sR = lof(R) + hif(R), sZ = lof(Z) + hif(Z); \
  float sX = lof(X) + hif(X), sH = lof(Hc) + hif(Hc); \
  float rv = sigf(sR + br), zv = sigf(sZ + bz); \
  float nv = tanf_fast(sX + bn + rv * (sH + bh)); \
  int bq = bb + 16 * (G); \
  float hprev = g_h[d][rs][bq][cb + c]; \
  float hnew = (1.f - zv) * nv + zv * hprev; \
  g_h[d][ws][bq][cb + c] = hnew; \
  out[(size_t)bq * OST + (size_t)t * (2 * Hh) + (size_t)d * Hh + cb + c] = hnew; }

// ---------------- persistent fused BiGRU ----------------
extern "C" __global__ void __launch_bounds__(NTHR, 1)
gru_persist(const float* __restrict__ data,
            const float* __restrict__ Wi_f, const float* __restrict__ bi_f,
            const float* __restrict__ Wh_f, const float* __restrict__ bhn_f,
            const float* __restrict__ Wi_b, const float* __restrict__ bi_b,
            const float* __restrict__ Wh_b, const float* __restrict__ bhn_b,
            float* __restrict__ out) {
    extern __shared__ float smem[];
    float* Ws  = smem;                                        // [24][772]
    ull*   red = (ull*)((char*)smem + WS_BYTES + 4 * VSLOTB); // overlaps h slots

    const int tid = threadIdx.x;
    const int bid = blockIdx.x;
    const int d   = bid >> 6;                 // direction
    const int cb  = (bid & 63) * 8;           // h-column base

    const float* Wi  = d ? Wi_b  : Wi_f;
    const float* Wh  = d ? Wh_b  : Wh_f;
    const float* bi  = d ? bi_b  : bi_f;
    const float* bhn = d ? bhn_b : bhn_f;

    // stage fused weights once: row j = gate*8 + cc, k-major
    for (int idx = tid; idx < 24 * 768; idx += NTHR) {
        int k = idx / 24, j = idx - k * 24;
        int g = j >> 3, cc = j & 7;
        int gcol = g * Hh + cb + cc;
        Ws[j * WSTRIDE + k] = (k < Ff) ? Wi[(size_t)k * (3 * Hh) + gcol]
                                       : Wh[(size_t)(k - Ff) * (3 * Hh) + gcol];
    }

    // zero my 8 h-columns of slot 0
    for (int i = tid; i < Bb * 8; i += NTHR)
        g_h[d][0][i >> 3][cb + (i & 7)] = 0.f;

    // split-K6: partition p handles k in [128p, 128p+128)
    const int p    = tid >> 7;
    const int tid2 = tid & 127;
    const int c    = tid2 >> 4;     // 0..7
    const int bb   = tid2 & 15;     // b base; cells: bb, bb+16, bb+32, bb+48
    const bool isx = (p < 2);       // partition is pure-x (k<256) or pure-h

    const float br = bi[cb + c];
    const float bz = bi[Hh + cb + c];
    const float bn = bi[2 * Hh + cb + c];
    const float bh = bhn[cb + c];

    const unsigned wsA = (unsigned)__cvta_generic_to_shared(Ws);
    const unsigned vsA = (unsigned)__cvta_generic_to_shared((char*)smem + WS_BYTES);
    const unsigned vb0 = (unsigned)(bb        * VROWB);
    const unsigned vb1 = (unsigned)((bb + 16) * VROWB);
    const unsigned vb2 = (unsigned)((bb + 32) * VROWB);
    const unsigned vb3 = (unsigned)((bb + 48) * VROWB);
    const unsigned wrB = wsA + (unsigned)((0  + c) * WSTRIDE) * 4u;
    const unsigned wzB = wsA + (unsigned)((8  + c) * WSTRIDE) * 4u;
    const unsigned wnB = wsA + (unsigned)((16 + c) * WSTRIDE) * 4u;

    const int K0 = p * 128;
    const unsigned slotA = vsA + (unsigned)(2 * p)     * VSLOTB;
    const unsigned slotB = vsA + (unsigned)(2 * p + 1) * VSLOTB;
    const int str = isx ? TFs : Hh;

    // x partitions pre-stage chunks c0,c1 for t=0 (x is constant data)
    if (isx) {
        const float* b0p = data + K0;
        stage32(slotA, b0p,      str, tid2);
        stage32(slotB, b0p + 32, str, tid2);
    }

    grid_barrier(d);   // h zeros + weights visible chip-wide

    // h partitions stage chunks c0,c1 for t=0
    if (!isx) {
        const float* b0p = &g_h[d][0][0][0] + (K0 - Ff);
        stage32(slotA, b0p,      str, tid2);
        stage32(slotB, b0p + 32, str, tid2);
    }

    for (int t = 0; t < Tt; ++t) {
        const int rs = t & 1;
        const int ws = rs ^ 1;
        const float* baseT = isx ? (data + (size_t)t * Ff + K0)
                                 : (&g_h[d][rs][0][0] + (K0 - Ff));
        const int tn = (t + 1 < Tt) ? t + 1 : t;   // clamp (avoid OOB at t=511)
        const float* baseN = data + (size_t)tn * Ff + K0;  // x-next only

        ull aR0=0,aR1=0,aR2=0,aR3=0, aZ0=0,aZ1=0,aZ2=0,aZ3=0;
        ull aN0=0,aN1=0,aN2=0,aN3=0;

        // j0: compute c0 (sA), then stage c2 -> sA
        cpa_wait<1>(); barp(p);
        COMPUTE_CHUNK(slotA, K0);
        barp(p);
        stage32(slotA, baseT + 64, str, tid2);

        // j1: compute c1 (sB), then stage c3 -> sB
        cpa_wait<1>(); barp(p);
        COMPUTE_CHUNK(slotB, K0 + 32);
        barp(p);
        stage32(slotB, baseT + 96, str, tid2);

        // j2: compute c2 (sA); x partitions stage next-step c0' -> sA
        cpa_wait<1>(); barp(p);
        COMPUTE_CHUNK(slotA, K0 + 64);
        barp(p);
        if (isx) stage32(slotA, baseN, TFs, tid2);

        // j3: compute c3 (sB); x partitions stage next-step c1' -> sB
        if (isx) { cpa_wait<1>(); } else { cpa_wait<0>(); }
        barp(p);
        COMPUTE_CHUNK(slotB, K0 + 96);
        if (isx) { barp(p); stage32(slotB, baseN + 32, TFs, tid2); }

        __syncthreads();

        if (p) {   // partitions 1..5 publish partials (conflict-free layout)
            ull* rp = red + (size_t)(p - 1) * 1536 + tid2;
            rp[0*128]=aR0; rp[1*128]=aR1; rp[2*128]=aR2;  rp[3*128]=aR3;
            rp[4*128]=aZ0; rp[5*128]=aZ1; rp[6*128]=aZ2;  rp[7*128]=aZ3;
            rp[8*128]=aN0; rp[9*128]=aN1; rp[10*128]=aN2; rp[11*128]=aN3;
        }
        __syncthreads();

        if (p == 0) {
            EPI(0, aR0, aZ0, aN0)
            EPI(1, aR1, aZ1, aN1)
            EPI(2, aR2, aZ2, aN2)
            EPI(3, aR3, aZ3, aN3)
        }

        grid_barrier(d);

        // h partitions stage chunks c0,c1 for step t+1 (new h now visible)
        if (!isx && t + 1 < Tt) {
            const float* bn2 = &g_h[d][ws][0][0] + (K0 - Ff);
            stage32(slotA, bn2,      str, tid2);
            stage32(slotB, bn2 + 32, str, tid2);
        }
    }
}

extern "C" void kernel_launch(void* const* d_in, const int* in_sizes, int n_in,
                              void* d_out, int out_size) {
    const float* data  = (const float*)d_in[0];
    const float* Wi_f  = (const float*)d_in[1];
    const float* bi_f  = (const float*)d_in[2];
    const float* Wh_f  = (const float*)d_in[3];
    const float* bhn_f = (const float*)d_in[4];
    const float* Wi_b  = (const float*)d_in[5];
    const float* bi_b  = (const float*)d_in[6];
    const float* Wh_b  = (const float*)d_in[7];
    const float* bhn_b = (const float*)d_in[8];
    float* out = (float*)d_out;

    cudaFuncSetAttribute(gru_persist, cudaFuncAttributeMaxDynamicSharedMemorySize, SMEM_BYTES);

    gru_persist<<<GRIDN, NTHR, SMEM_BYTES>>>(data, Wi_f, bi_f, Wh_f, bhn_f,
                                             Wi_b, bi_b, Wh_b, bhn_b, out);
}